// round 3
// baseline (speedup 1.0000x reference)
#include <cuda_runtime.h>
#include <cuda_bf16.h>
#include <cstdint>

// BarycentricPooling: per-node entropic-OT (Sinkhorn, log-domain) histogram onto a
// K=64 codebook, then segment-mean over B graphs.
//
// Shapes (fixed by the problem): N=20000 nodes, S=16, D=128, K=64, B=256,
// EPS=0.1, 20 scan iters + 1 extrapolation = 21 (g,f) sweeps.
//
// Strategy:
//   prep_kernel    : zero accumulators, transpose codebook to [d4][k] float4,
//                    precompute ||y_k||^2 and log2(softmax(log_prior)).
//   node_kernel    : 1 block (64 threads) per node. Thread t owns column k=t.
//                    - f32 SIMT GEMM for C (x staged in smem chunks, y in regs)
//                    - Sinkhorn in exp2/lg2 domain: P = -C*log2e/eps in regs,
//                      g-update thread-local, f-update via conflict-free smem
//                      tile + 1 shfl + 1 smem merge.
//                    - histogram + normalize + atomicAdd into per-graph sums.
//   final_kernel   : out[b][k] = counts>0 ? sums/counts : prior.
//
// log_a (uniform scalar) is dropped: it shifts f and g by equal/opposite uniform
// constants which cancel in the normalized histogram. log_b kept general.

#define SS    16
#define KK    64
#define DD    128
#define BMAX  256
#define ITERS 20
#define L2E_EPS 14.4269504088896340736f   // log2(e)/0.1

__device__ float4 g_ctf4[(DD/4)*KK];   // codebook transposed: [d4][k] -> float4 of 4 consecutive dims
__device__ float  g_y2[KK];            // ||codebook_k||^2
__device__ float  g_lb2[KK];           // log2(softmax(log_prior))
__device__ float  g_sums[BMAX*KK];
__device__ float  g_counts[BMAX];

__device__ __forceinline__ float ex2a(float x){ float y; asm("ex2.approx.ftz.f32 %0, %1;" : "=f"(y) : "f"(x)); return y; }
__device__ __forceinline__ float lg2a(float x){ float y; asm("lg2.approx.ftz.f32 %0, %1;" : "=f"(y) : "f"(x)); return y; }

// ---------------------------------------------------------------------------
__global__ void prep_kernel(const float* __restrict__ cb,
                            const float* __restrict__ lp)
{
    int i = blockIdx.x * blockDim.x + threadIdx.x;   // grid covers 16384
    if (i < BMAX*KK) g_sums[i] = 0.0f;
    if (i < BMAX)    g_counts[i] = 0.0f;
    if (i < (DD/4)*KK) {
        int d4 = i / KK, k = i % KK;
        const float* r = cb + k*DD + 4*d4;
        g_ctf4[i] = make_float4(r[0], r[1], r[2], r[3]);
    }
    if (i < KK) {
        float y2 = 0.0f;
        #pragma unroll 4
        for (int d = 0; d < DD; d++) { float v = cb[i*DD + d]; y2 += v*v; }
        g_y2[i] = y2;
        // log2 softmax of log_prior
        float mm = -1e30f;
        for (int k = 0; k < KK; k++) mm = fmaxf(mm, lp[k]);
        float ssum = 0.0f;
        for (int k = 0; k < KK; k++) ssum += __expf(lp[k] - mm);
        g_lb2[i] = (lp[i] - mm) * 1.4426950408889634f - lg2a(ssum);
    }
}

// ---------------------------------------------------------------------------
__global__ __launch_bounds__(64)
void node_kernel(const float* __restrict__ x,
                 const int*   __restrict__ bidx,
                 int n_nodes)
{
    int node = blockIdx.x;
    if (node >= n_nodes) return;
    int t = threadIdx.x;                  // 0..63, owns column k = t

    __shared__ float4 xsh4[SS][4];        // one 16-dim chunk of x, all 16 rows
    __shared__ float  x2sh[SS];
    __shared__ float  Msh[SS][KK+1];      // P + log2 b, padded to 65 floats/row
    __shared__ float  f2[SS];
    __shared__ float  g2s[KK];
    __shared__ float  redm[SS], rede[SS];
    __shared__ float  red2[2];

    const float* xg = x + (size_t)node * (SS*DD);

    // ---------------- GEMM: acc[s] = <x_s, y_t> ----------------
    float acc[SS];
    #pragma unroll
    for (int s = 0; s < SS; s++) acc[s] = 0.0f;
    float x2a = 0.0f;

    int ss = t >> 2, qq = t & 3;          // staging assignment
    #pragma unroll 1
    for (int c = 0; c < 8; c++) {
        // y chunk for this thread's column (coalesced, 16B stride across lanes)
        float4 yA = g_ctf4[(c*4+0)*KK + t];
        float4 yB = g_ctf4[(c*4+1)*KK + t];
        float4 yC = g_ctf4[(c*4+2)*KK + t];
        float4 yD = g_ctf4[(c*4+3)*KK + t];
        // stage x chunk: 16 rows x 16 dims
        xsh4[ss][qq] = *(const float4*)(xg + ss*DD + c*16 + qq*4);
        __syncthreads();
        #pragma unroll
        for (int s = 0; s < SS; s++) {
            float4 a0 = xsh4[s][0], a1 = xsh4[s][1], a2 = xsh4[s][2], a3 = xsh4[s][3];
            acc[s] += a0.x*yA.x + a0.y*yA.y + a0.z*yA.z + a0.w*yA.w
                    + a1.x*yB.x + a1.y*yB.y + a1.z*yB.z + a1.w*yB.w
                    + a2.x*yC.x + a2.y*yC.y + a2.z*yC.z + a2.w*yC.w
                    + a3.x*yD.x + a3.y*yD.y + a3.z*yD.z + a3.w*yD.w;
        }
        if (t < SS) {   // ||x_s||^2 partial (thread t handles row s=t)
            float4 a0 = xsh4[t][0], a1 = xsh4[t][1], a2 = xsh4[t][2], a3 = xsh4[t][3];
            x2a += a0.x*a0.x + a0.y*a0.y + a0.z*a0.z + a0.w*a0.w
                 + a1.x*a1.x + a1.y*a1.y + a1.z*a1.z + a1.w*a1.w
                 + a2.x*a2.x + a2.y*a2.y + a2.z*a2.z + a2.w*a2.w
                 + a3.x*a3.x + a3.y*a3.y + a3.z*a3.z + a3.w*a3.w;
        }
        __syncthreads();
    }
    if (t < SS) x2sh[t] = x2a;
    if (t < SS) f2[t] = 0.0f;
    __syncthreads();

    // ---------------- P = -C * log2e/eps ----------------
    float y2k  = g_y2[t];
    float lb2k = g_lb2[t];
    float P[SS];
    #pragma unroll
    for (int s = 0; s < SS; s++) {
        float Cv = fmaxf(x2sh[s] + y2k - 2.0f*acc[s], 0.0f);
        P[s] = -Cv * L2E_EPS;
        Msh[s][t] = P[s] + lb2k;          // f-update operand with log2(b) folded in
    }
    __syncthreads();

    // ---------------- Sinkhorn: 21 (g,f) sweeps in exp2 domain ----------------
    float G = 0.0f;
    const int fs = t & 15;                // f-update: row s
    const int fq = t >> 4;                // f-update: k-quarter
    float ar[SS];

    #pragma unroll 1
    for (int it = 0; it <= ITERS; it++) {
        // g-update (thread-local over s): G_k = -log2 sum_s 2^(F_s + P_sk)
        float m = -1e30f;
        #pragma unroll
        for (int s = 0; s < SS; s++) { ar[s] = f2[s] + P[s]; m = fmaxf(m, ar[s]); }
        float e = 0.0f;
        #pragma unroll
        for (int s = 0; s < SS; s++) e += ex2a(ar[s] - m);
        G = -(m + lg2a(e));
        g2s[t] = G;
        __syncthreads();

        // f-update: F_s = -log2 sum_k 2^(G_k + P_sk + lb2_k), k split in quarters
        float af[16];
        float mf = -1e30f;
        #pragma unroll
        for (int j = 0; j < 16; j++) {
            int k = fq*16 + j;
            af[j] = g2s[k] + Msh[fs][k];  // conflict-free: bank = (fs + 16*fq + j) % 32
            mf = fmaxf(mf, af[j]);
        }
        float ef = 0.0f;
        #pragma unroll
        for (int j = 0; j < 16; j++) ef += ex2a(af[j] - mf);
        // merge quarter pairs within warp (lane ^ 16)
        {
            float mo = __shfl_xor_sync(0xffffffffu, mf, 16);
            float eo = __shfl_xor_sync(0xffffffffu, ef, 16);
            float M2 = fmaxf(mf, mo);
            ef = ef*ex2a(mf - M2) + eo*ex2a(mo - M2);
            mf = M2;
        }
        // merge across warps via smem
        if (t >= 32 && t < 48) { redm[fs] = mf; rede[fs] = ef; }
        __syncthreads();
        if (t < 16) {
            float mo = redm[fs], eo = rede[fs];
            float M2 = fmaxf(mf, mo);
            float E  = ef*ex2a(mf - M2) + eo*ex2a(mo - M2);
            f2[fs] = -(M2 + lg2a(E));
        }
        __syncthreads();
    }

    // ---------------- histogram: h_k = 2^(G_k + lb2_k) * sum_s 2^(F_s + P_sk) ----
    float m = -1e30f;
    #pragma unroll
    for (int s = 0; s < SS; s++) { ar[s] = f2[s] + P[s]; m = fmaxf(m, ar[s]); }
    float e = 0.0f;
    #pragma unroll
    for (int s = 0; s < SS; s++) e += ex2a(ar[s] - m);
    float h2 = G + lb2k + m + lg2a(e);    // log2 of (unnormalized) hist_k

    // block max of h2
    float wm = h2;
    #pragma unroll
    for (int o = 16; o; o >>= 1) wm = fmaxf(wm, __shfl_xor_sync(0xffffffffu, wm, o));
    if ((t & 31) == 0) red2[t >> 5] = wm;
    __syncthreads();
    float Mx = fmaxf(red2[0], red2[1]);
    float hv = ex2a(h2 - Mx);
    float ws = hv;
    #pragma unroll
    for (int o = 16; o; o >>= 1) ws += __shfl_xor_sync(0xffffffffu, ws, o);
    __syncthreads();                      // red2 reuse
    if ((t & 31) == 0) red2[t >> 5] = ws;
    __syncthreads();
    float inv = 1.0f / (red2[0] + red2[1]);

    int b = bidx[node];
    atomicAdd(&g_sums[b*KK + t], hv * inv);
    if (t == 0) atomicAdd(&g_counts[b], 1.0f);
}

// ---------------------------------------------------------------------------
__global__ void final_kernel(float* __restrict__ out, int B)
{
    int b = blockIdx.x, k = threadIdx.x;
    if (b >= B) return;
    float c = g_counts[b];
    float v = (c > 0.0f) ? (g_sums[b*KK + k] / c) : ex2a(g_lb2[k]);
    out[b*KK + k] = v;
}

// ---------------------------------------------------------------------------
extern "C" void kernel_launch(void* const* d_in, const int* in_sizes, int n_in,
                              void* d_out, int out_size)
{
    const float* x    = (const float*)d_in[0];   // [N,16,128] f32
    const int*   bi   = (const int*)  d_in[1];   // [N] int32
    const float* cb   = (const float*)d_in[2];   // [64,128] f32
    const float* lp   = (const float*)d_in[3];   // [64] f32
    int N = in_sizes[1];
    int B = out_size / KK;
    if (B > BMAX) B = BMAX;

    prep_kernel<<<64, 256>>>(cb, lp);
    node_kernel<<<N, 64>>>(x, bi, N);
    final_kernel<<<B, KK>>>((float*)d_out, B);
}

// round 4
// speedup vs baseline: 1.0740x; 1.0740x over previous
#include <cuda_runtime.h>
#include <cuda_bf16.h>
#include <cstdint>

// BarycentricPooling — trajectory-exact stabilized-linear Sinkhorn.
//
// N=20000 nodes, S=16, D=128, K=64, B=256, eps=0.1, 21 (g,f) sweeps.
//
// Per node (1 block, 64 threads, thread t owns codebook column k=t):
//   1. f32 GEMM via packed fma.rn.f32x2 (FFMA2): dot[s] = <x_s, y_t>.
//   2. P_sk = -C_sk*log2(e)/eps  (C = ||x||^2+||y||^2-2dot, clamped >= 0).
//   3. Sweep 1 in log2 domain (f=0 init) -> F1_s, G1_k  (handles the huge
//      per-row ||x||^2 dynamic range once).
//   4. Absorb: W*_sk = 2^(F1+G1+P) (regs, g-direction), Wb = W* * b_k
//      (regs, f-direction quarters). W* is doubly stabilized: row sums of
//      W*b = 1 (f fresh), column maxes >= 2^-10 (g fresh) -> f32-safe.
//   5. 20 linear sweeps on residual scalings:
//         V = rcp(sum_s u*W*),  u = rcp(sum_k V*W*b)
//      (exactly the reference updates, zero EX2), re-absorbing every 4.
//   6. hist_k = b_k * V_k * sum_s u_s W*_sk  (shifts cancel exactly),
//      normalize, atomicAdd into per-graph sums.
// log_a (uniform) dropped: shifts cancel in the normalized histogram
// (verified empirically in R3: rel_err 7.7e-6).

#define SS    16
#define KK    64
#define DD    128
#define BMAX  256
#define L2E_EPS 14.4269504088896340736f   // log2(e)/0.1

__device__ float4 g_ctf4[(DD/4)*KK];   // codebook transposed: [d4][k] float4
__device__ float  g_y2[KK];            // ||y_k||^2
__device__ float  g_lb2[KK];           // log2(softmax(log_prior))
__device__ float  g_bk[KK];            // softmax(log_prior)
__device__ float  g_sums[BMAX*KK];
__device__ float  g_counts[BMAX];

__device__ __forceinline__ float ex2a(float x){ float y; asm("ex2.approx.ftz.f32 %0, %1;" : "=f"(y) : "f"(x)); return y; }
__device__ __forceinline__ float lg2a(float x){ float y; asm("lg2.approx.ftz.f32 %0, %1;" : "=f"(y) : "f"(x)); return y; }
__device__ __forceinline__ float rcpa(float x){ float y; asm("rcp.approx.ftz.f32 %0, %1;" : "=f"(y) : "f"(x)); return y; }
// packed f32x2 fma: lo/hi lanes independent (SASS FFMA2)
__device__ __forceinline__ void ffma2(unsigned long long& d, unsigned long long a, unsigned long long b){
    asm("fma.rn.f32x2 %0, %1, %2, %0;" : "+l"(d) : "l"(a), "l"(b));
}
__device__ __forceinline__ float unpack_add(unsigned long long v){
    float lo = __uint_as_float((unsigned)(v & 0xffffffffull));
    float hi = __uint_as_float((unsigned)(v >> 32));
    return lo + hi;
}

// ---------------------------------------------------------------------------
__global__ void prep_kernel(const float* __restrict__ cb,
                            const float* __restrict__ lp)
{
    int i = blockIdx.x * blockDim.x + threadIdx.x;
    if (i < BMAX*KK) g_sums[i] = 0.0f;
    if (i < BMAX)    g_counts[i] = 0.0f;
    if (i < (DD/4)*KK) {
        int d4 = i / KK, k = i % KK;
        const float* r = cb + k*DD + 4*d4;
        g_ctf4[i] = make_float4(r[0], r[1], r[2], r[3]);
    }
    if (i < KK) {
        float y2 = 0.0f;
        #pragma unroll 4
        for (int d = 0; d < DD; d++) { float v = cb[i*DD + d]; y2 += v*v; }
        g_y2[i] = y2;
        float mm = -1e30f;
        for (int k = 0; k < KK; k++) mm = fmaxf(mm, lp[k]);
        float ssum = 0.0f;
        for (int k = 0; k < KK; k++) ssum += __expf(lp[k] - mm);
        float lb2 = (lp[i] - mm) * 1.4426950408889634f - lg2a(ssum);
        g_lb2[i] = lb2;
        g_bk[i]  = ex2a(lb2);
    }
}

// ---------------------------------------------------------------------------
__global__ __launch_bounds__(64)
void node_kernel(const float* __restrict__ x,
                 const int*   __restrict__ bidx,
                 int n_nodes)
{
    int node = blockIdx.x;
    if (node >= n_nodes) return;
    int t = threadIdx.x;                  // 0..63, owns column k = t
    const int fs = t & 15;                // f-direction: row
    const int fq = t >> 4;                // f-direction: k-quarter

    __shared__ float xsh[SS*DD];          // x tile, row-major [s][d] (8KB)
    __shared__ float x2sh[SS];
    __shared__ float Msh[SS][KK+1];       // P + log2(b), padded
    __shared__ float f2[SS];              // F1 (log2) then u-hat (linear)
    __shared__ float g2s[KK];             // G1 (log2) then V-hat (linear)
    __shared__ float redm[SS], rede[SS];
    __shared__ float red2[2];

    // ---------------- stage x ----------------
    {
        const float4* xg4 = (const float4*)(x + (size_t)node * (SS*DD));
        float4* xs4 = (float4*)xsh;
        #pragma unroll
        for (int j = 0; j < 8; j++) xs4[t + 64*j] = xg4[t + 64*j];
    }
    __syncthreads();

    // ---------------- GEMM via FFMA2: dot[s] = <x_s, y_t> ----------------
    unsigned long long acc2[SS];
    #pragma unroll
    for (int s = 0; s < SS; s++) acc2[s] = 0ull;

    #pragma unroll 2
    for (int d4 = 0; d4 < 32; d4++) {
        const ulonglong2 yp = ((const ulonglong2*)g_ctf4)[d4*KK + t];
        #pragma unroll
        for (int s = 0; s < SS; s++) {
            ulonglong2 xp = *(const ulonglong2*)(xsh + s*DD + d4*4);
            ffma2(acc2[s], xp.x, yp.x);
            ffma2(acc2[s], xp.y, yp.y);
        }
    }
    float dot[SS];
    #pragma unroll
    for (int s = 0; s < SS; s++) dot[s] = unpack_add(acc2[s]);

    // ---------------- ||x_s||^2 : (s = fs, quarter of d = fq) ----------------
    {
        unsigned long long p2 = 0ull;
        #pragma unroll
        for (int i = 0; i < 8; i++) {
            ulonglong2 xp = *(const ulonglong2*)(xsh + fs*DD + fq*32 + i*4);
            ffma2(p2, xp.x, xp.x);
            ffma2(p2, xp.y, xp.y);
        }
        float x2p = unpack_add(p2);
        x2p += __shfl_xor_sync(0xffffffffu, x2p, 16);
        if (t >= 32 && t < 48) redm[fs] = x2p;
        __syncthreads();
        if (t < 16) x2sh[fs] = x2p + redm[fs];
        __syncthreads();
    }

    // ---------------- P = -C * log2e/eps ----------------
    float y2k  = g_y2[t];
    float lb2k = g_lb2[t];
    float P[SS];
    #pragma unroll
    for (int s = 0; s < SS; s++) {
        float Cv = fmaxf(x2sh[s] + y2k - 2.0f*dot[s], 0.0f);
        P[s] = -Cv * L2E_EPS;
        Msh[s][t] = P[s] + lb2k;
    }
    __syncthreads();

    // ---------------- sweep 1 (log2 domain, F=0 init) ----------------
    float G1;
    {
        // g-update: G1_k = -log2 sum_s 2^(P_sk)
        float m = -1e30f;
        #pragma unroll
        for (int s = 0; s < SS; s++) m = fmaxf(m, P[s]);
        float e = 0.0f;
        #pragma unroll
        for (int s = 0; s < SS; s++) e += ex2a(P[s] - m);
        G1 = -(m + lg2a(e));
        g2s[t] = G1;
        __syncthreads();

        // f-update: F1_s = -log2 sum_k 2^(G1_k + P_sk + lb2_k)
        float af[16];
        float mf = -1e30f;
        #pragma unroll
        for (int j = 0; j < 16; j++) {
            int k = fq*16 + j;
            af[j] = g2s[k] + Msh[fs][k];
            mf = fmaxf(mf, af[j]);
        }
        float ef = 0.0f;
        #pragma unroll
        for (int j = 0; j < 16; j++) ef += ex2a(af[j] - mf);
        {
            float mo = __shfl_xor_sync(0xffffffffu, mf, 16);
            float eo = __shfl_xor_sync(0xffffffffu, ef, 16);
            float M2 = fmaxf(mf, mo);
            ef = ef*ex2a(mf - M2) + eo*ex2a(mo - M2);
            mf = M2;
        }
        if (t >= 32 && t < 48) { redm[fs] = mf; rede[fs] = ef; }
        __syncthreads();
        if (t < 16) {
            float mo = redm[fs], eo = rede[fs];
            float M2 = fmaxf(mf, mo);
            float E  = ef*ex2a(mf - M2) + eo*ex2a(mo - M2);
            f2[fs] = -(M2 + lg2a(E));
        }
        __syncthreads();
    }

    // ---------------- absorb (F1,G1) into the kernel ----------------
    // W[s]  = 2^(F1_s + G1_t + P_st)           (g-direction, own column)
    // Wbq[j]= 2^(F1_fs + G1_k + P_fs,k + lb2_k) (f-direction, row fs, quarter fq)
    float W[SS], Wbq[16];
    {
        float F1fs = f2[fs];
        #pragma unroll
        for (int j = 0; j < 16; j++) {
            int k = fq*16 + j;
            Wbq[j] = ex2a(F1fs + g2s[k] + Msh[fs][k]);
        }
        #pragma unroll
        for (int s = 0; s < SS; s++)
            W[s] = ex2a(f2[s] + G1 + P[s]);
    }
    __syncthreads();
    if (t < 16) f2[t] = 1.0f;     // u-hat init (residual potential = 0)
    __syncthreads();

    // ---------------- 20 linear sweeps ----------------
    float vcur = 1.0f;
    #pragma unroll 1
    for (int it = 1; it <= 20; it++) {
        // g: V_k = rcp(sum_s u_s W_sk)
        float cs = 0.0f;
        #pragma unroll
        for (int s = 0; s < SS; s++) cs = fmaf(f2[s], W[s], cs);
        vcur = rcpa(fmaxf(cs, 1e-30f));
        g2s[t] = vcur;
        __syncthreads();

        // f: u_s = rcp(sum_k V_k Wb_sk)
        float rs = 0.0f;
        #pragma unroll
        for (int j = 0; j < 16; j++) rs = fmaf(g2s[fq*16 + j], Wbq[j], rs);
        rs += __shfl_xor_sync(0xffffffffu, rs, 16);
        if (t >= 32 && t < 48) redm[fs] = rs;
        __syncthreads();
        if (t < 16) f2[fs] = rcpa(fmaxf(rs + redm[fs], 1e-30f));
        __syncthreads();

        // re-absorb every 4 sweeps to keep residual scalings near 1
        if ((it & 3) == 0 && it != 20) {
            float us[SS];
            #pragma unroll
            for (int s = 0; s < SS; s++) { us[s] = f2[s]; W[s] *= us[s]*vcur; }
            #pragma unroll
            for (int j = 0; j < 16; j++) Wbq[j] *= us[fs]*g2s[fq*16 + j];
            __syncthreads();
            if (t < 16) f2[t] = 1.0f;
            __syncthreads();
        }
    }

    // ---------------- histogram: h_k = b_k * V_k * sum_s u_s W_sk ----------------
    float cs2 = 0.0f;
    #pragma unroll
    for (int s = 0; s < SS; s++) cs2 = fmaf(f2[s], W[s], cs2);
    float hk = g_bk[t] * vcur * cs2;

    float ws = hk;
    #pragma unroll
    for (int o = 16; o; o >>= 1) ws += __shfl_xor_sync(0xffffffffu, ws, o);
    if ((t & 31) == 0) red2[t >> 5] = ws;
    __syncthreads();
    float inv = rcpa(fmaxf(red2[0] + red2[1], 1e-30f));

    int b = bidx[node];
    atomicAdd(&g_sums[b*KK + t], hk * inv);
    if (t == 0) atomicAdd(&g_counts[b], 1.0f);
}

// ---------------------------------------------------------------------------
__global__ void final_kernel(float* __restrict__ out, int B)
{
    int b = blockIdx.x, k = threadIdx.x;
    if (b >= B) return;
    float c = g_counts[b];
    float v = (c > 0.0f) ? (g_sums[b*KK + k] / c) : g_bk[k];
    out[b*KK + k] = v;
}

// ---------------------------------------------------------------------------
extern "C" void kernel_launch(void* const* d_in, const int* in_sizes, int n_in,
                              void* d_out, int out_size)
{
    const float* x    = (const float*)d_in[0];   // [N,16,128] f32
    const int*   bi   = (const int*)  d_in[1];   // [N] int32
    const float* cb   = (const float*)d_in[2];   // [64,128] f32
    const float* lp   = (const float*)d_in[3];   // [64] f32
    int N = in_sizes[1];
    int B = out_size / KK;
    if (B > BMAX) B = BMAX;

    prep_kernel<<<64, 256>>>(cb, lp);
    node_kernel<<<N, 64>>>(x, bi, N);
    final_kernel<<<B, KK>>>((float*)d_out, B);
}